// round 11
// baseline (speedup 1.0000x reference)
#include <cuda_runtime.h>
#include <cuda_bf16.h>

#define KDIM  64
#define LOG2E 1.4426950408889634f
#define LN2   0.6931471805599453f
#define DIST  4          // emit prefetch distance (steps), power of 2
#define TH    -1000000.0f
#define FULL  0xffffffffu

typedef unsigned long long ull;

__device__ __forceinline__ ull pk2(float a, float b) {
    ull r; asm("mov.b64 %0, {%1, %2};" : "=l"(r) : "f"(a), "f"(b)); return r;
}
__device__ __forceinline__ ull fma2(ull a, ull b, ull c) {
    ull d; asm("fma.rn.f32x2 %0, %1, %2, %3;" : "=l"(d) : "l"(a), "l"(b), "l"(c)); return d;
}
__device__ __forceinline__ ull add2(ull a, ull b) {
    ull d; asm("add.rn.f32x2 %0, %1, %2;" : "=l"(d) : "l"(a), "l"(b)); return d;
}
__device__ __forceinline__ float ex2f(float x) {
    float y; asm("ex2.approx.f32 %0, %1;" : "=f"(y) : "f"(x)); return y;
}
__device__ __forceinline__ float lg2f(float x) {
    float y; asm("lg2.approx.f32 %0, %1;" : "=f"(y) : "f"(x)); return y;
}
__device__ __forceinline__ float scalbn_fast(float x, int d) {
    return __int_as_float(__float_as_int(x) - (d << 23));
}
__device__ __forceinline__ float unpack_add(ull v) {
    float lo, hi; asm("mov.b64 {%0, %1}, %2;" : "=f"(lo), "=f"(hi) : "l"(v));
    return lo + hi;
}

// CTA = 128 threads = 2 rows x 2 warps. Each lane owns ONE state (st = h*32+lane).
// Exp-domain recursion (no per-step lg2/ex2):
//   e_j(t) = [ m_t ? (sum_i e_i(t-1) E[i][j]) * 2^(emit_j lg2e) : e_j(t-1) ] * 2^(-d)
// d = exponent-field of e_0(t-1) (read from sh_e, no broadcast var, exact integer
// accumulation in C2i). Per-step sync = ONE plain __syncthreads (BAR floor ~7cyc).
// Mask votes: per-warp __all_sync into a 4-deep slot ring (slot = t & 3), written
// one step ahead pre-barrier, read one step ahead post-barrier -> every aliasing
// write/read pair is separated by >= 1 barrier. tv/point computed warp-uniformly
// (no lane-0 branches). E built from GLOBAL trans (no sh_trans). Steps t >= N run
// masked (m = 0): pure frame shift, result invariant.
__global__ __launch_bounds__(128, 1) void crf_fwd_kernel(
    const float* __restrict__ y_pred,   // [B, N, K]
    const float* __restrict__ trans,    // [K, K]
    const int*   __restrict__ y_true,   // [B, N]
    float*       __restrict__ out,      // [B]
    int N, int B)
{
    __shared__ __align__(16) float sh_e[2][2][KDIM];   // [row-in-CTA][buf][state]
    __shared__ unsigned sh_mv[4][2][2];                // [slot][row][warp-half]
    __shared__ float sh_red[2][2][2];                  // [row][half][{se, point}]

    const int tid  = threadIdx.x;
    const int lane = tid & 31;
    const int wid  = tid >> 5;
    const int r    = wid >> 1;                  // row within CTA (0/1)
    const int h    = wid & 1;                   // state half (0/1)
    int row = blockIdx.x * 2 + r;
    if (row >= B) row = B - 1;                  // clamp (dup row writes same value)
    const int st = h * 32 + lane;               // my state

    // My E column from GLOBAL: Ec[k] packs trans rows (2k, 2k+1), col st.
    ull Ec[KDIM / 2];
#pragma unroll
    for (int k = 0; k < KDIM / 2; ++k) {
        Ec[k] = pk2(__expf(trans[(2 * k) * KDIM + st]),
                    __expf(trans[(2 * k + 1) * KDIM + st]));
    }

    const float* yrow = y_pred + (size_t)row * N * KDIM;
    const int*   trow = y_true + (size_t)row * N;

    // ---- t = 0 ----
    float y0 = yrow[st];
    int yt0 = trow[0];
    sh_mv[0][r][h] = __all_sync(FULL, y0 > TH);

    // prime emit ring (steps 1..DIST)
    float ring[DIST];
#pragma unroll
    for (int p = 1; p <= DIST; ++p) {
        int tt = (p < N) ? p : (N - 1);
        ring[p & (DIST - 1)] = yrow[(size_t)tt * KDIM + st];
    }
    {   // vote for step 1 into slot 1
        unsigned v1 = __all_sync(FULL, ring[1 & (DIST - 1)] > TH);
        sh_mv[1][r][h] = (1 < N) ? v1 : 0u;
    }
    __syncthreads();                            // publishes slots 0, 1

    unsigned m0 = sh_mv[0][r][0] & sh_mv[0][r][1];
    float fm0 = m0 ? 1.0f : 0.0f;
    float e = ex2f((y0 * fm0) * LOG2E);
    float point = (st == yt0) ? y0 * fm0 : 0.0f;
    int   C2i = 0;
    float tv = 0.0f;
    sh_e[r][0][st] = e;
    float fmprev = fm0;
    unsigned mcur = sh_mv[1][r][0] & sh_mv[1][r][1];
    float fmcur = mcur ? 1.0f : 0.0f;

    // tv / label pipeline (warp-uniform; LDGs L1-resident after warmup)
    int yt_cur = trow[(1 < N) ? 1 : (N - 1)];
    int yt_nx  = trow[(2 < N) ? 2 : (N - 1)];
    float trv_cur = trans[yt0 * KDIM + yt_cur];
    __syncthreads();                            // t=0 e-stores visible

    // slots: MSN = (T+1) & 3 written pre-bar; mnext read post-bar from MSN.
#define STEP(T, RP, RPN, BUF, PBUF, MSN)                                             \
    {                                                                                \
        float yv = ring[RP];                                                         \
        int tt = ((T) + DIST < N) ? ((T) + DIST) : (N - 1);                          \
        ring[RP] = yrow[(size_t)tt * KDIM + st];                                     \
        unsigned vn = __all_sync(FULL, ring[RPN] > TH);                              \
        sh_mv[MSN][r][h] = ((T) + 1 < N) ? vn : 0u;   /* vote for step T+1 */        \
        int tn = ((T) + 2 < N) ? ((T) + 2) : (N - 1);                                \
        int yt_nx2 = trow[tn];                                                       \
        float trv_next = trans[yt_cur * KDIM + yt_nx];                               \
        float p = ex2f(yv * (fmcur * LOG2E));   /* MUFU pre-barrier */               \
        __syncthreads();        /* publishes e(t-1) + slot (T+1) votes */            \
        unsigned mnext = sh_mv[MSN][r][0] & sh_mv[MSN][r][1];                        \
        int d = (int)((unsigned)__float_as_int(sh_e[r][PBUF][0]) >> 23) - 127;       \
        ull A0 = 0, A1 = 0, A2 = 0, A3 = 0;                                          \
        const ulonglong2* ep = (const ulonglong2*)sh_e[r][PBUF];                     \
        _Pragma("unroll")                                                            \
        for (int k = 0; k < KDIM / 4; ++k) {                                         \
            ulonglong2 ee = ep[k];                                                   \
            if (k & 1) { A2 = fma2(ee.x, Ec[2 * k], A2);                             \
                         A3 = fma2(ee.y, Ec[2 * k + 1], A3); }                       \
            else       { A0 = fma2(ee.x, Ec[2 * k], A0);                             \
                         A1 = fma2(ee.y, Ec[2 * k + 1], A1); }                       \
        }                                                                            \
        float s = unpack_add(add2(add2(A0, A1), add2(A2, A3)));                      \
        float q = mcur ? s * p : e;                                                  \
        e = scalbn_fast(q, d);                                                       \
        C2i += d;                                                                    \
        point += (st == yt_cur) ? yv * fmcur : 0.0f;                                 \
        tv += trv_cur * (fmprev * fmcur);                                            \
        sh_e[r][BUF][st] = e;                                                        \
        fmprev = fmcur;                                                              \
        mcur = mnext; fmcur = mnext ? 1.0f : 0.0f;                                   \
        trv_cur = trv_next; yt_cur = yt_nx; yt_nx = yt_nx2;                          \
    }

    // ---- main loop: t0 === 1 (mod 4); overflow steps run masked (harmless) ----
    for (int t0 = 1; t0 < N; t0 += 4) {
        STEP(t0 + 0, 1, 2, 1, 0, 2)
        STEP(t0 + 1, 2, 3, 0, 1, 3)
        STEP(t0 + 2, 3, 0, 1, 0, 0)
        STEP(t0 + 3, 0, 1, 0, 1, 1)
    }
#undef STEP

    // ---- epilogue: reduce 2^(w) and point over the row's 64 states ----
    float se = e, pp = point;
#pragma unroll
    for (int o = 16; o > 0; o >>= 1) {
        se += __shfl_xor_sync(FULL, se, o);
        pp += __shfl_xor_sync(FULL, pp, o);
    }
    if (lane == 0) { sh_red[r][h][0] = se; sh_red[r][h][1] = pp; }
    __syncthreads();
    if (h == 0 && lane == 0) {
        float seT = sh_red[r][0][0] + sh_red[r][1][0];
        float ppT = sh_red[r][0][1] + sh_red[r][1][1];
        out[row] = LN2 * ((float)C2i + lg2f(seT)) - (ppT + tv);
    }
}

extern "C" void kernel_launch(void* const* d_in, const int* in_sizes, int n_in,
                              void* d_out, int out_size) {
    const float* y_pred = (const float*)d_in[0];   // [B, N, K] f32
    const float* trans  = (const float*)d_in[1];   // [K, K]    f32
    const int*   y_true = (const int*)  d_in[2];   // [B, N]    i32
    float* out = (float*)d_out;                    // [B]       f32

    int B = out_size;                  // 512
    int N = in_sizes[2] / B;           // 1024
    int blocks = (B + 1) / 2;          // 256 CTAs, 2 rows each
    crf_fwd_kernel<<<blocks, 128>>>(y_pred, trans, y_true, out, N, B);
}